// round 8
// baseline (speedup 1.0000x reference)
#include <cuda_runtime.h>

// KV cache append — expressed as 16 contiguous D2D memcpy nodes.
//   inputs: cached_k [B,S,D], cached_v [B,S,D], new_k [B,NEW,D], new_v [B,NEW,D]  (fp32)
//   output: [out_k ; out_v] packed, each [B, S+NEW, D]
// B=4, S=4096, NEW=16, D=4096.
// R8 experiment: per (kv, batch) the output is two contiguous runs:
//   rows [0,S)      <- cached[b]  (64 MB, contiguous)
//   rows [S, S+NEW) <- new[b]     (256 KB, contiguous)
// cudaMemcpyAsync D2D is graph-capturable per the harness rules; this lets the
// driver choose its copy path (CE DMA or its own copy kernel) instead of our
// SM kernel, probing whether a non-LSU path beats the ~86% DRAM plateau.

static constexpr int    B    = 4;
static constexpr int    S    = 4096;
static constexpr int    NEWT = 16;
static constexpr int    D    = 4096;
static constexpr int    SOUT = S + NEWT;                 // 4112
static constexpr size_t ROW_BYTES    = (size_t)D * sizeof(float);       // 16 KB
static constexpr size_t CACHED_BYTES = (size_t)S * ROW_BYTES;           // 64 MB
static constexpr size_t NEW_BYTES    = (size_t)NEWT * ROW_BYTES;        // 256 KB
static constexpr size_t OUT_BATCH    = (size_t)SOUT * ROW_BYTES;        // per (kv,b)

extern "C" void kernel_launch(void* const* d_in, const int* in_sizes, int n_in,
                              void* d_out, int out_size)
{
    const char* cached_k = (const char*)d_in[0];
    const char* cached_v = (const char*)d_in[1];
    const char* new_k    = (const char*)d_in[2];
    const char* new_v    = (const char*)d_in[3];
    char* out = (char*)d_out;

    for (int kv = 0; kv < 2; kv++) {
        const char* cached = kv ? cached_v : cached_k;
        const char* nw     = kv ? new_v    : new_k;
        for (int b = 0; b < B; b++) {
            char* dst = out + ((size_t)(kv * B + b)) * OUT_BATCH;
            cudaMemcpyAsync(dst,
                            cached + (size_t)b * CACHED_BYTES,
                            CACHED_BYTES, cudaMemcpyDeviceToDevice, 0);
            cudaMemcpyAsync(dst + CACHED_BYTES,
                            nw + (size_t)b * NEW_BYTES,
                            NEW_BYTES, cudaMemcpyDeviceToDevice, 0);
        }
    }
}

// round 9
// speedup vs baseline: 1.2085x; 1.2085x over previous
#include <cuda_runtime.h>

// KV cache append — pure HBM streaming copy.  FINAL KERNEL (= R3, passed 2x).
//   inputs: cached_k [B,S,D], cached_v [B,S,D], new_k [B,NEW,D], new_v [B,NEW,D]  (fp32)
//   output: [out_k ; out_v] packed, each [B, S+NEW, D]
// B=4, S=4096, NEW=16, D=4096.
// 8 independent float4 per thread (MLP_p1=8), one block = 2 contiguous seq
// rows (32KB), streaming ld/st hints (.cs).
// Converged at the path-independent LTS chip cap (~6300 B/cyc ≈ 6.9 TB/s):
// DRAM ~86% busy, issue ~4%, no SM-side lever remains (verified against
// MLP=4/8, 256-bit v8, persistent pipelined grids, and memcpy-node graphs).

static constexpr int B    = 4;
static constexpr int S    = 4096;
static constexpr int NEWT = 16;
static constexpr int D    = 4096;
static constexpr int SOUT = S + NEWT;          // 4112
static constexpr int DV   = D / 4;             // 1024 float4 per row
static constexpr int TPB  = 256;               // threads per block
static constexpr int F4_PER_THREAD = 8;        // 2048 float4 = 2 rows per block
static constexpr int ROWS_PER_BLOCK = (TPB * F4_PER_THREAD) / DV;  // 2

__global__ __launch_bounds__(TPB)
void kv_append_kernel(const float4* __restrict__ cached_k,
                      const float4* __restrict__ cached_v,
                      const float4* __restrict__ new_k,
                      const float4* __restrict__ new_v,
                      float4* __restrict__ out)
{
    // grid: x = SOUT/2 (2056) -> seq row pair, y = 2*B (8) -> kv/batch
    const int s  = blockIdx.x * ROWS_PER_BLOCK; // 0,2,..,4110 (pair never crosses
                                                // the S=4096 boundary: S is even)
    const int zb = blockIdx.y;                  // 0..7
    const int kv = zb >> 2;                     // 0 = K, 1 = V
    const int b  = zb & 3;                      // batch

    const float4* __restrict__ src;
    if (s < S) {
        const float4* __restrict__ cached = kv ? cached_v : cached_k;
        src = cached + (size_t)(b * S + s) * DV;
    } else {
        const float4* __restrict__ nw = kv ? new_v : new_k;
        src = nw + (size_t)(b * NEWT + (s - S)) * DV;
    }
    float4* __restrict__ dst = out + ((size_t)(kv * B + b) * SOUT + s) * DV;

    const int c = threadIdx.x;

    // Front-batched independent streaming loads (MLP_p1 = 8).
    float4 v0 = __ldcs(src + c);
    float4 v1 = __ldcs(src + c + 1 * TPB);
    float4 v2 = __ldcs(src + c + 2 * TPB);
    float4 v3 = __ldcs(src + c + 3 * TPB);
    float4 v4 = __ldcs(src + c + 4 * TPB);
    float4 v5 = __ldcs(src + c + 5 * TPB);
    float4 v6 = __ldcs(src + c + 6 * TPB);
    float4 v7 = __ldcs(src + c + 7 * TPB);

    __stcs(dst + c,           v0);
    __stcs(dst + c + 1 * TPB, v1);
    __stcs(dst + c + 2 * TPB, v2);
    __stcs(dst + c + 3 * TPB, v3);
    __stcs(dst + c + 4 * TPB, v4);
    __stcs(dst + c + 5 * TPB, v5);
    __stcs(dst + c + 6 * TPB, v6);
    __stcs(dst + c + 7 * TPB, v7);
}

extern "C" void kernel_launch(void* const* d_in, const int* in_sizes, int n_in,
                              void* d_out, int out_size)
{
    const float4* cached_k = (const float4*)d_in[0];
    const float4* cached_v = (const float4*)d_in[1];
    const float4* new_k    = (const float4*)d_in[2];
    const float4* new_v    = (const float4*)d_in[3];
    float4* out = (float4*)d_out;

    dim3 grid(SOUT / ROWS_PER_BLOCK, 2 * B);
    kv_append_kernel<<<grid, TPB>>>(cached_k, cached_v, new_k, new_v, out);
}

// round 10
// speedup vs baseline: 1.2093x; 1.0006x over previous
#include <cuda_runtime.h>

// KV cache append — pure HBM/LTS streaming copy.
//   inputs: cached_k [B,S,D], cached_v [B,S,D], new_k [B,NEW,D], new_v [B,NEW,D]  (fp32)
//   output: [out_k ; out_v] packed, each [B, S+NEW, D]
// B=4, S=4096, NEW=16, D=4096.
// R10: final micro-probe — TPB=512, 4 independent float4 per thread
// (2 contiguous rows per block, 8224 blocks), streaming (.cs) ld/st.
// Converged family: all shapes plateau at the path-independent LTS chip cap
// (~6300 B/cyc ≈ 6.8-6.9 TB/s, DRAM ~86% busy).

static constexpr int B    = 4;
static constexpr int S    = 4096;
static constexpr int NEWT = 16;
static constexpr int D    = 4096;
static constexpr int SOUT = S + NEWT;          // 4112
static constexpr int DV   = D / 4;             // 1024 float4 per row
static constexpr int TPB  = 512;               // threads per block
static constexpr int F4_PER_THREAD = 4;        // 2048 float4 = 2 rows per block
static constexpr int ROWS_PER_BLOCK = (TPB * F4_PER_THREAD) / DV;  // 2

__global__ __launch_bounds__(TPB)
void kv_append_kernel(const float4* __restrict__ cached_k,
                      const float4* __restrict__ cached_v,
                      const float4* __restrict__ new_k,
                      const float4* __restrict__ new_v,
                      float4* __restrict__ out)
{
    // grid: x = SOUT/2 (2056) -> seq row pair, y = 2*B (8) -> kv/batch
    const int s  = blockIdx.x * ROWS_PER_BLOCK; // 0,2,..,4110 (pair never crosses
                                                // the S=4096 boundary: S is even)
    const int zb = blockIdx.y;                  // 0..7
    const int kv = zb >> 2;                     // 0 = K, 1 = V
    const int b  = zb & 3;                      // batch

    const float4* __restrict__ src;
    if (s < S) {
        const float4* __restrict__ cached = kv ? cached_v : cached_k;
        src = cached + (size_t)(b * S + s) * DV;
    } else {
        const float4* __restrict__ nw = kv ? new_v : new_k;
        src = nw + (size_t)(b * NEWT + (s - S)) * DV;
    }
    float4* __restrict__ dst = out + ((size_t)(kv * B + b) * SOUT + s) * DV;

    const int c = threadIdx.x;

    // Front-batched independent streaming loads (MLP_p1 = 4).
    float4 v0 = __ldcs(src + c);
    float4 v1 = __ldcs(src + c + 1 * TPB);
    float4 v2 = __ldcs(src + c + 2 * TPB);
    float4 v3 = __ldcs(src + c + 3 * TPB);

    __stcs(dst + c,           v0);
    __stcs(dst + c + 1 * TPB, v1);
    __stcs(dst + c + 2 * TPB, v2);
    __stcs(dst + c + 3 * TPB, v3);
}

extern "C" void kernel_launch(void* const* d_in, const int* in_sizes, int n_in,
                              void* d_out, int out_size)
{
    const float4* cached_k = (const float4*)d_in[0];
    const float4* cached_v = (const float4*)d_in[1];
    const float4* new_k    = (const float4*)d_in[2];
    const float4* new_v    = (const float4*)d_in[3];
    float4* out = (float4*)d_out;

    dim3 grid(SOUT / ROWS_PER_BLOCK, 2 * B);
    kv_append_kernel<<<grid, TPB>>>(cached_k, cached_v, new_k, new_v, out);
}

// round 11
// speedup vs baseline: 1.2149x; 1.0047x over previous
#include <cuda_runtime.h>

// KV cache append — pure HBM/LTS streaming copy.  FINAL KERNEL.
//   inputs: cached_k [B,S,D], cached_v [B,S,D], new_k [B,NEW,D], new_v [B,NEW,D]  (fp32)
//   output: [out_k ; out_v] packed, each [B, S+NEW, D]
// B=4, S=4096, NEW=16, D=4096.
//
// Shape: 8 independent float4 per thread (front-batched, MLP_p1=8), one block
// = 2 contiguous seq rows (32KB), 16448 blocks x 256 threads, streaming (.cs)
// loads and stores.
//
// Converged at the B300 path-independent LTS chip cap (~6300 B/cyc ≈ 6.9 TB/s):
// DRAM ~86% busy, HBM ~6.86 TB/s, issue ~4%. Verified neutral/worse across:
// MLP=1/4/8, 256-bit v8 ld/st, block 256/512, persistent pipelined grids,
// cudaMemcpyAsync graph nodes. Traffic (1.055 GB) is irreducible for an exact
// concatenation, so ~150us kernel time is the hardware floor.

static constexpr int B    = 4;
static constexpr int S    = 4096;
static constexpr int NEWT = 16;
static constexpr int D    = 4096;
static constexpr int SOUT = S + NEWT;          // 4112
static constexpr int DV   = D / 4;             // 1024 float4 per row
static constexpr int TPB  = 256;               // threads per block
static constexpr int F4_PER_THREAD = 8;        // 2048 float4 = 2 rows per block
static constexpr int ROWS_PER_BLOCK = (TPB * F4_PER_THREAD) / DV;  // 2

__global__ __launch_bounds__(TPB)
void kv_append_kernel(const float4* __restrict__ cached_k,
                      const float4* __restrict__ cached_v,
                      const float4* __restrict__ new_k,
                      const float4* __restrict__ new_v,
                      float4* __restrict__ out)
{
    // grid: x = SOUT/2 (2056) -> seq row pair, y = 2*B (8) -> kv/batch
    const int s  = blockIdx.x * ROWS_PER_BLOCK; // 0,2,..,4110 (pair never crosses
                                                // the S=4096 boundary: S is even)
    const int zb = blockIdx.y;                  // 0..7
    const int kv = zb >> 2;                     // 0 = K, 1 = V
    const int b  = zb & 3;                      // batch

    const float4* __restrict__ src;
    if (s < S) {
        const float4* __restrict__ cached = kv ? cached_v : cached_k;
        src = cached + (size_t)(b * S + s) * DV;
    } else {
        const float4* __restrict__ nw = kv ? new_v : new_k;
        src = nw + (size_t)(b * NEWT + (s - S)) * DV;
    }
    float4* __restrict__ dst = out + ((size_t)(kv * B + b) * SOUT + s) * DV;

    const int c = threadIdx.x;

    // Front-batched independent streaming loads (MLP_p1 = 8).
    float4 v0 = __ldcs(src + c);
    float4 v1 = __ldcs(src + c + 1 * TPB);
    float4 v2 = __ldcs(src + c + 2 * TPB);
    float4 v3 = __ldcs(src + c + 3 * TPB);
    float4 v4 = __ldcs(src + c + 4 * TPB);
    float4 v5 = __ldcs(src + c + 5 * TPB);
    float4 v6 = __ldcs(src + c + 6 * TPB);
    float4 v7 = __ldcs(src + c + 7 * TPB);

    __stcs(dst + c,           v0);
    __stcs(dst + c + 1 * TPB, v1);
    __stcs(dst + c + 2 * TPB, v2);
    __stcs(dst + c + 3 * TPB, v3);
    __stcs(dst + c + 4 * TPB, v4);
    __stcs(dst + c + 5 * TPB, v5);
    __stcs(dst + c + 6 * TPB, v6);
    __stcs(dst + c + 7 * TPB, v7);
}

extern "C" void kernel_launch(void* const* d_in, const int* in_sizes, int n_in,
                              void* d_out, int out_size)
{
    const float4* cached_k = (const float4*)d_in[0];
    const float4* cached_v = (const float4*)d_in[1];
    const float4* new_k    = (const float4*)d_in[2];
    const float4* new_v    = (const float4*)d_in[3];
    float4* out = (float4*)d_out;

    dim3 grid(SOUT / ROWS_PER_BLOCK, 2 * B);
    kv_append_kernel<<<grid, TPB>>>(cached_k, cached_v, new_k, new_v, out);
}